// round 7
// baseline (speedup 1.0000x reference)
#include <cuda_runtime.h>
#include <cstdint>

// ---------------------------------------------------------------------------
// EMGNetQuantized: fused BinaryNet inference, XLA-matched fp32 numerics.
// R7: conv0 rewritten lane=oc, channel-inner PAIR smem layout, f32x2 packed
// FMA (per-lane IEEE identical to the passing scalar chain), ballot instead
// of atomics. The FMA sequence per accumulator (ky->kx->ic, acc from 0,
// bias after, unfused bn) is bit-identical to round 6.
// ---------------------------------------------------------------------------

__device__ __align__(16) uint32_t g_w2bits[32 * 9];       // [oc][ky*3+kx], bit=ic
__device__ __align__(16) uint32_t g_wfcbits[516 * 36];    // [o][word], bit=col%32
__device__ float g_inv1[32], g_sh1[32];                   // bn1 scale/shift
__device__ float g_inv2[32], g_sh2[32];                   // bn2 scale/shift
__device__ float g_sc3[516], g_sh3[516];                  // bn3 scale/shift

__global__ void prep_kernel(const float* __restrict__ w2,
                            const float* __restrict__ wfc,
                            const float* __restrict__ g1, const float* __restrict__ be1,
                            const float* __restrict__ m1, const float* __restrict__ v1,
                            const float* __restrict__ g2, const float* __restrict__ be2,
                            const float* __restrict__ m2, const float* __restrict__ v2,
                            const float* __restrict__ g3, const float* __restrict__ be3,
                            const float* __restrict__ m3, const float* __restrict__ v3) {
    int t = blockIdx.x * blockDim.x + threadIdx.x;
    if (t < 288) {
        int oc = t / 9, k = t % 9;
        uint32_t w = 0u;
        #pragma unroll 4
        for (int ic = 0; ic < 32; ic++)
            if (w2[oc * 288 + ic * 9 + k] >= 0.f) w |= (1u << ic);
        g_w2bits[t] = w;
    } else if (t < 288 + 516 * 36) {
        int j = t - 288;
        int o = j / 36, c = j % 36;
        const float* row = wfc + o * 1152 + c * 32;
        uint32_t w = 0u;
        #pragma unroll 4
        for (int b = 0; b < 32; b++)
            if (row[b] >= 0.f) w |= (1u << b);
        g_wfcbits[j] = w;
    } else if (t < 288 + 18576 + 32) {
        int c = t - (288 + 18576);
        float inv = __fdiv_rn(g1[c], __fsqrt_rn(__fadd_rn(v1[c], 1e-5f)));
        g_inv1[c] = inv;
        g_sh1[c]  = __fsub_rn(be1[c], __fmul_rn(m1[c], inv));
    } else if (t < 288 + 18576 + 64) {
        int c = t - (288 + 18576 + 32);
        float inv = __fdiv_rn(g2[c], __fsqrt_rn(__fadd_rn(v2[c], 1e-5f)));
        g_inv2[c] = inv;
        g_sh2[c]  = __fsub_rn(be2[c], __fmul_rn(m2[c], inv));
    } else if (t < 288 + 18576 + 64 + 516) {
        int c = t - (288 + 18576 + 64);
        float inv = __fdiv_rn(g3[c], __fsqrt_rn(__fadd_rn(v3[c], 1e-5f)));
        g_sc3[c] = inv;
        g_sh3[c] = __fsub_rn(be3[c], __fmul_rn(m3[c], inv));
    }
}

// ---- f32x2 helpers (per-lane IEEE RN fma; identical numerics to scalar) ----
__device__ __forceinline__ unsigned long long fma2(unsigned long long a,
                                                   unsigned long long b,
                                                   unsigned long long c) {
    unsigned long long d;
    asm("fma.rn.f32x2 %0, %1, %2, %3;" : "=l"(d) : "l"(a), "l"(b), "l"(c));
    return d;
}
__device__ __forceinline__ unsigned long long pack2(float lo, float hi) {
    unsigned long long r;
    asm("mov.b64 %0, {%1, %2};" : "=l"(r) : "f"(lo), "f"(hi));
    return r;
}
__device__ __forceinline__ float2 unpack2(unsigned long long v) {
    float lo, hi;
    asm("mov.b64 {%0, %1}, %2;" : "=f"(lo), "=f"(hi) : "l"(v));
    return make_float2(lo, hi);
}

__global__ __launch_bounds__(256, 3) void fused_kernel(
        const float* __restrict__ x,
        const float* __restrict__ w0,
        const float* __restrict__ b0,
        const float* __restrict__ wlast,
        const float* __restrict__ blast,
        float* __restrict__ out) {
    // sxp[y][xpair 0..14][ic 0..7] = float2{ x(ic,y,xp), x(ic,y,xp+1) }
    // row stride 240 floats (960B) -> bank pattern rotates per y.
    __shared__ float    sxp[16 * 15 * 16];     // 15360 B
    __shared__ float    sw0t[2304];            // [k=(ky*3+kx)*8+ic][oc]  9216 B
    __shared__ uint32_t s1bits[196];           // conv0 sign bits, bit = channel
    __shared__ uint32_t sw2b[288];
    __shared__ uint32_t fcb[36];               // 1152 FC input bits
    __shared__ float    h3[516];               // bn3/htanh output

    const int tid  = threadIdx.x;
    const int lane = tid & 31;
    const int wid  = tid >> 5;
    const int img  = blockIdx.x;

    // ---- Phase A: stage image (pair layout) + transposed weights -----------
    {
        const float* xg = x + (size_t)img * 2048;
        for (int i = tid; i < 1920; i += 256) {
            int xp = i % 15;
            int t2 = i / 15;
            int ic = t2 & 7;
            int yy = t2 >> 3;
            float a = xg[ic * 256 + yy * 16 + xp];
            float b = xg[ic * 256 + yy * 16 + xp + 1];
            *(float2*)&sxp[(yy * 15 + xp) * 16 + ic * 2] = make_float2(a, b);
        }
        for (int i = tid; i < 2304; i += 256) {
            int oc = i & 31, k = i >> 5;
            int ic = k & 7, kk = k >> 3;          // kk = ky*3+kx
            sw0t[i] = w0[oc * 72 + ic * 9 + kk];
        }
        for (int i = tid; i < 288; i += 256) sw2b[i] = g_w2bits[i];
    }
    __syncthreads();

    // ---- Phase B: conv0 via f32x2, lane = oc, ballot -> sign bits ----------
    // Each warp handles output rows y = wid, wid+8. Per acc half the FMA
    // chain is exactly (ky,kx,ic) ascending, acc from 0, bias after.
    {
        float bias = b0[lane];
        float inv  = g_inv1[lane];
        float sh   = g_sh1[lane];
        for (int y = wid; y < 14; y += 8) {
            unsigned long long acc[7];
            #pragma unroll
            for (int p = 0; p < 7; p++) acc[p] = 0ull;

            #pragma unroll
            for (int ky = 0; ky < 3; ky++) {
                #pragma unroll
                for (int kx = 0; kx < 3; kx++) {
                    unsigned long long wp[8];
                    #pragma unroll
                    for (int ic = 0; ic < 8; ic++) {
                        float w = sw0t[((ky * 3 + kx) * 8 + ic) * 32 + lane];
                        wp[ic] = pack2(w, w);
                    }
                    #pragma unroll
                    for (int p = 0; p < 7; p++) {
                        const ulonglong2* rp = (const ulonglong2*)
                            &sxp[((y + ky) * 15 + (2 * p + kx)) * 16];
                        ulonglong2 q0 = rp[0], q1 = rp[1], q2 = rp[2], q3 = rp[3];
                        acc[p] = fma2(q0.x, wp[0], acc[p]);
                        acc[p] = fma2(q0.y, wp[1], acc[p]);
                        acc[p] = fma2(q1.x, wp[2], acc[p]);
                        acc[p] = fma2(q1.y, wp[3], acc[p]);
                        acc[p] = fma2(q2.x, wp[4], acc[p]);
                        acc[p] = fma2(q2.y, wp[5], acc[p]);
                        acc[p] = fma2(q3.x, wp[6], acc[p]);
                        acc[p] = fma2(q3.y, wp[7], acc[p]);
                    }
                }
            }
            #pragma unroll
            for (int p = 0; p < 7; p++) {
                float2 av = unpack2(acc[p]);
                float h0 = __fadd_rn(av.x, bias);
                float v0 = __fadd_rn(__fmul_rn(h0, inv), sh);
                uint32_t m0 = __ballot_sync(0xffffffffu, v0 >= 0.f);
                float h1 = __fadd_rn(av.y, bias);
                float v1 = __fadd_rn(__fmul_rn(h1, inv), sh);
                uint32_t m1 = __ballot_sync(0xffffffffu, v1 >= 0.f);
                if (lane == 0) {
                    s1bits[y * 14 + 2 * p]     = m0;
                    s1bits[y * 14 + 2 * p + 1] = m1;
                }
            }
        }
    }
    __syncthreads();

    // ---- Phase C: binary conv2 + integer maxpool + bn2 sign -> FC bits -----
    // task = (c, pooled y, pooled x); one ballot per 32 tasks -> fcb word.
    for (int task = tid; task < 1152; task += 256) {
        int c  = task / 36;
        int r  = task % 36;
        int py = r / 6, px = r % 6;
        uint32_t wk[9];
        #pragma unroll
        for (int k = 0; k < 9; k++) wk[k] = sw2b[c * 9 + k];

        int maxd = -10000;
        #pragma unroll
        for (int dy = 0; dy < 2; dy++) {
            #pragma unroll
            for (int dx = 0; dx < 2; dx++) {
                int y  = py * 2 + dy;
                int xx = px * 2 + dx;
                int p = 0;
                #pragma unroll
                for (int ky = 0; ky < 3; ky++) {
                    #pragma unroll
                    for (int kx = 0; kx < 3; kx++)
                        p += __popc(s1bits[(y + ky) * 14 + xx + kx] ^ wk[ky * 3 + kx]);
                }
                int d = 288 - 2 * p;               // exact integer dot
                maxd = max(maxd, d);
            }
        }
        float v = __fadd_rn(__fmul_rn((float)maxd, g_inv2[c]), g_sh2[c]);
        uint32_t m = __ballot_sync(0xffffffffu, v >= 0.f);
        if ((tid & 31) == 0) fcb[task >> 5] = m;
    }
    __syncthreads();

    // ---- Phase D: binary FC (1152 -> 516, exact int) + bn3 + hardtanh ------
    for (int o = tid; o < 516; o += 256) {
        const uint4* wr = (const uint4*)&g_wfcbits[o * 36];
        int p = 0;
        #pragma unroll
        for (int q = 0; q < 9; q++) {
            uint4 wv = wr[q];
            const uint32_t* fb = &fcb[q * 4];
            p += __popc(fb[0] ^ wv.x) + __popc(fb[1] ^ wv.y)
               + __popc(fb[2] ^ wv.z) + __popc(fb[3] ^ wv.w);
        }
        float d = (float)(1152 - 2 * p);
        float h = __fadd_rn(__fmul_rn(d, g_sc3[o]), g_sh3[o]);  // bn3 UNFUSED
        h3[o] = fminf(1.f, fmaxf(-1.f, h));
    }
    __syncthreads();

    // ---- Phase E: final 516x10 GEMV (fp32) + bias --------------------------
    if (tid < 160) {
        int i = tid >> 4;       // output index 0..9
        int s = tid & 15;       // 16-lane reduction slot
        const float* wr = wlast + i * 516;
        float acc = 0.f;
        for (int j = s; j < 516; j += 16)
            acc = __fmaf_rn(h3[j], wr[j], acc);
        #pragma unroll
        for (int off = 8; off; off >>= 1)
            acc = __fadd_rn(acc, __shfl_xor_sync(0xffffffffu, acc, off, 16));
        if (s == 0)
            out[(size_t)img * 10 + i] = __fadd_rn(acc, blast[i]);
    }
}

extern "C" void kernel_launch(void* const* d_in, const int* in_sizes, int n_in,
                              void* d_out, int out_size) {
    const float* x     = (const float*)d_in[0];
    const float* w0    = (const float*)d_in[1];
    const float* b0    = (const float*)d_in[2];
    const float* g1    = (const float*)d_in[3];
    const float* be1   = (const float*)d_in[4];
    const float* m1    = (const float*)d_in[5];
    const float* v1    = (const float*)d_in[6];
    const float* w2    = (const float*)d_in[7];
    const float* g2    = (const float*)d_in[8];
    const float* be2   = (const float*)d_in[9];
    const float* m2    = (const float*)d_in[10];
    const float* v2    = (const float*)d_in[11];
    const float* wfc   = (const float*)d_in[12];
    const float* g3    = (const float*)d_in[13];
    const float* be3   = (const float*)d_in[14];
    const float* m3    = (const float*)d_in[15];
    const float* v3    = (const float*)d_in[16];
    const float* wlast = (const float*)d_in[17];
    const float* blast = (const float*)d_in[18];
    float* out = (float*)d_out;

    prep_kernel<<<76, 256>>>(w2, wfc, g1, be1, m1, v1,
                             g2, be2, m2, v2, g3, be3, m3, v3);
    fused_kernel<<<8192, 256>>>(x, w0, b0, wlast, blast, out);
}

// round 8
// speedup vs baseline: 1.2284x; 1.2284x over previous
#include <cuda_runtime.h>
#include <cstdint>

// ---------------------------------------------------------------------------
// EMGNetQuantized fused BinaryNet inference, XLA-matched fp32 numerics.
// R8: conv0 register-tiled: thread = (oc-half x 2 outputs) = 16oc x 2x tile,
// f32x2 packed FMA over oc pairs (bit-identical per-lane IEEE chains,
// ky->kx->ic ascending, acc from 0, bias after, unfused bn decisions).
// Dup-splat smem input layout {v,v} -> LDS.64 == splat. Weights
// pre-transposed in prep (coalesced per-CTA load). Phases C/D/E as in R7.
// ---------------------------------------------------------------------------

__device__ __align__(16) uint32_t g_w2bits[32 * 9];       // [oc][ky*3+kx], bit=ic
__device__ __align__(16) uint32_t g_wfcbits[516 * 36];    // [o][word], bit=col%32
__device__ __align__(16) float    g_w0p[2304];            // [k=(ky3+kx)*8+ic][oc]
__device__ float g_inv1[32], g_sh1[32];                   // bn1 scale/shift
__device__ float g_inv2[32], g_sh2[32];                   // bn2 scale/shift
__device__ float g_sc3[516], g_sh3[516];                  // bn3 scale/shift

__global__ void prep_kernel(const float* __restrict__ w0,
                            const float* __restrict__ w2,
                            const float* __restrict__ wfc,
                            const float* __restrict__ g1, const float* __restrict__ be1,
                            const float* __restrict__ m1, const float* __restrict__ v1,
                            const float* __restrict__ g2, const float* __restrict__ be2,
                            const float* __restrict__ m2, const float* __restrict__ v2,
                            const float* __restrict__ g3, const float* __restrict__ be3,
                            const float* __restrict__ m3, const float* __restrict__ v3) {
    int t = blockIdx.x * blockDim.x + threadIdx.x;
    if (t < 288) {
        int oc = t / 9, k = t % 9;
        uint32_t w = 0u;
        #pragma unroll 4
        for (int ic = 0; ic < 32; ic++)
            if (w2[oc * 288 + ic * 9 + k] >= 0.f) w |= (1u << ic);
        g_w2bits[t] = w;
    } else if (t < 288 + 18576) {
        int j = t - 288;
        int o = j / 36, c = j % 36;
        const float* row = wfc + o * 1152 + c * 32;
        uint32_t w = 0u;
        #pragma unroll 4
        for (int b = 0; b < 32; b++)
            if (row[b] >= 0.f) w |= (1u << b);
        g_wfcbits[j] = w;
    } else if (t < 288 + 18576 + 32) {
        int c = t - (288 + 18576);
        float inv = __fdiv_rn(g1[c], __fsqrt_rn(__fadd_rn(v1[c], 1e-5f)));
        g_inv1[c] = inv;
        g_sh1[c]  = __fsub_rn(be1[c], __fmul_rn(m1[c], inv));
    } else if (t < 288 + 18576 + 64) {
        int c = t - (288 + 18576 + 32);
        float inv = __fdiv_rn(g2[c], __fsqrt_rn(__fadd_rn(v2[c], 1e-5f)));
        g_inv2[c] = inv;
        g_sh2[c]  = __fsub_rn(be2[c], __fmul_rn(m2[c], inv));
    } else if (t < 288 + 18576 + 64 + 516) {
        int c = t - (288 + 18576 + 64);
        float inv = __fdiv_rn(g3[c], __fsqrt_rn(__fadd_rn(v3[c], 1e-5f)));
        g_sc3[c] = inv;
        g_sh3[c] = __fsub_rn(be3[c], __fmul_rn(m3[c], inv));
    } else if (t < 288 + 18576 + 64 + 516 + 2304) {
        // transpose w0 -> [k][oc] so per-CTA loads are linear/coalesced
        int j  = t - (288 + 18576 + 64 + 516);
        int oc = j & 31;
        int r  = j >> 5;
        int ic = r & 7;
        int kk = r >> 3;                  // ky*3+kx
        g_w0p[j] = w0[oc * 72 + ic * 9 + kk];
    }
}

// ---- f32x2 helpers (per-lane IEEE RN fma; bit-identical to scalar) ---------
__device__ __forceinline__ unsigned long long fma2(unsigned long long a,
                                                   unsigned long long b,
                                                   unsigned long long c) {
    unsigned long long d;
    asm("fma.rn.f32x2 %0, %1, %2, %3;" : "=l"(d) : "l"(a), "l"(b), "l"(c));
    return d;
}
__device__ __forceinline__ float2 unpack2(unsigned long long v) {
    float lo, hi;
    asm("mov.b64 {%0, %1}, %2;" : "=f"(lo), "=f"(hi) : "l"(v));
    return make_float2(lo, hi);
}

#define XP 19   // sxd2 row pitch in float2 (bank-rotating)

__global__ __launch_bounds__(256, 2) void fused_kernel(
        const float* __restrict__ x,
        const float* __restrict__ b0,
        const float* __restrict__ wlast,
        const float* __restrict__ blast,
        float* __restrict__ out) {
    __shared__ float2   sxd2[8 * 16 * XP];     // input dup pairs {v,v}, 19456 B
    __shared__ __align__(16) float swp[2304];  // weights [k][oc] (pair-ready)
    __shared__ uint32_t s1bits[196];           // conv0 sign bits, bit = channel
    __shared__ uint32_t sw2b[288];
    __shared__ uint32_t fcb[36];
    __shared__ float    h3[516];
    __shared__ float    sb0[32], sinv1[32], ssh1[32];

    const int tid = threadIdx.x;
    const int img = blockIdx.x;

    // ---- Phase A: stage image (dup layout), weights (linear), constants ----
    {
        const float4* xin = (const float4*)(x + (size_t)img * 2048);
        for (int i = tid; i < 512; i += 256) {
            float4 v = xin[i];
            int ic = i >> 6;
            int rm = i & 63;
            int yy = rm >> 2;
            int x0 = (rm & 3) * 4;
            float2* dst = &sxd2[(ic * 16 + yy) * XP + x0];
            dst[0] = make_float2(v.x, v.x);
            dst[1] = make_float2(v.y, v.y);
            dst[2] = make_float2(v.z, v.z);
            dst[3] = make_float2(v.w, v.w);
        }
        for (int i = tid; i < 2304; i += 256) swp[i] = g_w0p[i];
        for (int i = tid; i < 288;  i += 256) sw2b[i] = g_w2bits[i];
        for (int i = tid; i < 196;  i += 256) s1bits[i] = 0u;
        if (tid < 32) {
            sb0[tid]   = b0[tid];
            sinv1[tid] = g_inv1[tid];
            ssh1[tid]  = g_sh1[tid];
        }
    }
    __syncthreads();

    // ---- Phase B: conv0, 16oc x 2x register tile, f32x2 over oc pairs ------
    // task = (h, xg, y): h = oc-half (16 ocs), xg = x pair, y = row. 196 tasks.
    if (tid < 196) {
        int y  = tid % 14;
        int t2 = tid / 14;
        int xg = t2 % 7;
        int h  = t2 / 7;
        int x0 = 2 * xg;

        unsigned long long acc[16];          // [xi*8 + p], p = ocpair in half
        #pragma unroll
        for (int i = 0; i < 16; i++) acc[i] = 0ull;

        #pragma unroll
        for (int ky = 0; ky < 3; ky++) {
            #pragma unroll
            for (int kx = 0; kx < 3; kx++) {
                #pragma unroll
                for (int ic = 0; ic < 8; ic++) {
                    int k8 = (ky * 3 + kx) * 8 + ic;
                    const float2* rr = &sxd2[(ic * 16 + y + ky) * XP + x0 + kx];
                    unsigned long long s0 = *(const unsigned long long*)&rr[0];
                    unsigned long long s1 = *(const unsigned long long*)&rr[1];
                    const ulonglong2* wq = (const ulonglong2*)&swp[k8 * 32 + h * 16];
                    ulonglong2 w01 = wq[0], w23 = wq[1], w45 = wq[2], w67 = wq[3];
                    acc[0]  = fma2(s0, w01.x, acc[0]);
                    acc[8]  = fma2(s1, w01.x, acc[8]);
                    acc[1]  = fma2(s0, w01.y, acc[1]);
                    acc[9]  = fma2(s1, w01.y, acc[9]);
                    acc[2]  = fma2(s0, w23.x, acc[2]);
                    acc[10] = fma2(s1, w23.x, acc[10]);
                    acc[3]  = fma2(s0, w23.y, acc[3]);
                    acc[11] = fma2(s1, w23.y, acc[11]);
                    acc[4]  = fma2(s0, w45.x, acc[4]);
                    acc[12] = fma2(s1, w45.x, acc[12]);
                    acc[5]  = fma2(s0, w45.y, acc[5]);
                    acc[13] = fma2(s1, w45.y, acc[13]);
                    acc[6]  = fma2(s0, w67.x, acc[6]);
                    acc[14] = fma2(s1, w67.x, acc[14]);
                    acc[7]  = fma2(s0, w67.y, acc[7]);
                    acc[15] = fma2(s1, w67.y, acc[15]);
                }
            }
        }
        // epilogue: bias + bn1 sign (unfused), build 16-bit masks, one OR per x
        uint32_t m0 = 0u, m1 = 0u;
        #pragma unroll
        for (int p = 0; p < 8; p++) {
            float biasL = sb0[h * 16 + 2 * p],     biasH = sb0[h * 16 + 2 * p + 1];
            float invL  = sinv1[h * 16 + 2 * p],   invH  = sinv1[h * 16 + 2 * p + 1];
            float shL   = ssh1[h * 16 + 2 * p],    shH   = ssh1[h * 16 + 2 * p + 1];
            float2 a0 = unpack2(acc[p]);
            float2 a1 = unpack2(acc[8 + p]);
            if (__fadd_rn(__fmul_rn(__fadd_rn(a0.x, biasL), invL), shL) >= 0.f)
                m0 |= 1u << (2 * p);
            if (__fadd_rn(__fmul_rn(__fadd_rn(a0.y, biasH), invH), shH) >= 0.f)
                m0 |= 1u << (2 * p + 1);
            if (__fadd_rn(__fmul_rn(__fadd_rn(a1.x, biasL), invL), shL) >= 0.f)
                m1 |= 1u << (2 * p);
            if (__fadd_rn(__fmul_rn(__fadd_rn(a1.y, biasH), invH), shH) >= 0.f)
                m1 |= 1u << (2 * p + 1);
        }
        atomicOr(&s1bits[y * 14 + x0],     m0 << (16 * h));
        atomicOr(&s1bits[y * 14 + x0 + 1], m1 << (16 * h));
    }
    __syncthreads();

    // ---- Phase C: binary conv2 + integer maxpool + bn2 sign -> FC bits -----
    for (int task = tid; task < 1152; task += 256) {
        int c  = task / 36;
        int r  = task % 36;
        int py = r / 6, px = r % 6;
        uint32_t wk[9];
        #pragma unroll
        for (int k = 0; k < 9; k++) wk[k] = sw2b[c * 9 + k];

        int maxd = -10000;
        #pragma unroll
        for (int dy = 0; dy < 2; dy++) {
            #pragma unroll
            for (int dx = 0; dx < 2; dx++) {
                int y  = py * 2 + dy;
                int xx = px * 2 + dx;
                int p = 0;
                #pragma unroll
                for (int ky = 0; ky < 3; ky++) {
                    #pragma unroll
                    for (int kx = 0; kx < 3; kx++)
                        p += __popc(s1bits[(y + ky) * 14 + xx + kx] ^ wk[ky * 3 + kx]);
                }
                int d = 288 - 2 * p;               // exact integer dot
                maxd = max(maxd, d);
            }
        }
        float v = __fadd_rn(__fmul_rn((float)maxd, g_inv2[c]), g_sh2[c]);
        uint32_t m = __ballot_sync(0xffffffffu, v >= 0.f);
        if ((tid & 31) == 0) fcb[task >> 5] = m;
    }
    __syncthreads();

    // ---- Phase D: binary FC (1152 -> 516, exact int) + bn3 + hardtanh ------
    for (int o = tid; o < 516; o += 256) {
        const uint4* wr = (const uint4*)&g_wfcbits[o * 36];
        int p = 0;
        #pragma unroll
        for (int q = 0; q < 9; q++) {
            uint4 wv = wr[q];
            const uint32_t* fb = &fcb[q * 4];
            p += __popc(fb[0] ^ wv.x) + __popc(fb[1] ^ wv.y)
               + __popc(fb[2] ^ wv.z) + __popc(fb[3] ^ wv.w);
        }
        float d = (float)(1152 - 2 * p);
        float h = __fadd_rn(__fmul_rn(d, g_sc3[o]), g_sh3[o]);  // bn3 UNFUSED
        h3[o] = fminf(1.f, fmaxf(-1.f, h));
    }
    __syncthreads();

    // ---- Phase E: final 516x10 GEMV (fp32) + bias --------------------------
    if (tid < 160) {
        int i = tid >> 4;       // output index 0..9
        int s = tid & 15;       // 16-lane reduction slot
        const float* wr = wlast + i * 516;
        float acc = 0.f;
        for (int j = s; j < 516; j += 16)
            acc = __fmaf_rn(h3[j], wr[j], acc);
        #pragma unroll
        for (int off = 8; off; off >>= 1)
            acc = __fadd_rn(acc, __shfl_xor_sync(0xffffffffu, acc, off, 16));
        if (s == 0)
            out[(size_t)img * 10 + i] = __fadd_rn(acc, blast[i]);
    }
}

extern "C" void kernel_launch(void* const* d_in, const int* in_sizes, int n_in,
                              void* d_out, int out_size) {
    const float* x     = (const float*)d_in[0];
    const float* w0    = (const float*)d_in[1];
    const float* b0    = (const float*)d_in[2];
    const float* g1    = (const float*)d_in[3];
    const float* be1   = (const float*)d_in[4];
    const float* m1    = (const float*)d_in[5];
    const float* v1    = (const float*)d_in[6];
    const float* w2    = (const float*)d_in[7];
    const float* g2    = (const float*)d_in[8];
    const float* be2   = (const float*)d_in[9];
    const float* m2    = (const float*)d_in[10];
    const float* v2    = (const float*)d_in[11];
    const float* wfc   = (const float*)d_in[12];
    const float* g3    = (const float*)d_in[13];
    const float* be3   = (const float*)d_in[14];
    const float* m3    = (const float*)d_in[15];
    const float* v3    = (const float*)d_in[16];
    const float* wlast = (const float*)d_in[17];
    const float* blast = (const float*)d_in[18];
    float* out = (float*)d_out;

    // 288 + 18576 + 32 + 32 + 516 + 2304 = 21748 prep tasks
    prep_kernel<<<85, 256>>>(w0, w2, wfc, g1, be1, m1, v1,
                             g2, be2, m2, v2, g3, be3, m3, v3);
    fused_kernel<<<8192, 256>>>(x, b0, wlast, blast, out);
}

// round 9
// speedup vs baseline: 1.3943x; 1.1350x over previous
#include <cuda_runtime.h>
#include <cstdint>

// ---------------------------------------------------------------------------
// EMGNetQuantized fused BinaryNet inference, XLA-matched fp32 numerics.
// R9: wavefront diet. Phase B: plain smem + scalar LDS.32 + register splat
// packs (FMA2 chains bit-identical to R8: ky->kx->ic, acc from 0, bias after,
// unfused bn). Phase C: sliding register window, thread=(channel,pooled row).
// Phase D: fcb read as uint4. Phases A/E as R8.
// ---------------------------------------------------------------------------

__device__ __align__(16) uint32_t g_w2bits[32 * 9];       // [oc][ky*3+kx], bit=ic
__device__ __align__(16) uint32_t g_wfcbits[516 * 36];    // [o][word], bit=col%32
__device__ __align__(16) float    g_w0p[2304];            // [k=(ky3+kx)*8+ic][oc]
__device__ float g_inv1[32], g_sh1[32];                   // bn1 scale/shift
__device__ float g_inv2[32], g_sh2[32];                   // bn2 scale/shift
__device__ float g_sc3[516], g_sh3[516];                  // bn3 scale/shift

__global__ void prep_kernel(const float* __restrict__ w0,
                            const float* __restrict__ w2,
                            const float* __restrict__ wfc,
                            const float* __restrict__ g1, const float* __restrict__ be1,
                            const float* __restrict__ m1, const float* __restrict__ v1,
                            const float* __restrict__ g2, const float* __restrict__ be2,
                            const float* __restrict__ m2, const float* __restrict__ v2,
                            const float* __restrict__ g3, const float* __restrict__ be3,
                            const float* __restrict__ m3, const float* __restrict__ v3) {
    int t = blockIdx.x * blockDim.x + threadIdx.x;
    if (t < 288) {
        int oc = t / 9, k = t % 9;
        uint32_t w = 0u;
        #pragma unroll 4
        for (int ic = 0; ic < 32; ic++)
            if (w2[oc * 288 + ic * 9 + k] >= 0.f) w |= (1u << ic);
        g_w2bits[t] = w;
    } else if (t < 288 + 18576) {
        int j = t - 288;
        int o = j / 36, c = j % 36;
        const float* row = wfc + o * 1152 + c * 32;
        uint32_t w = 0u;
        #pragma unroll 4
        for (int b = 0; b < 32; b++)
            if (row[b] >= 0.f) w |= (1u << b);
        g_wfcbits[j] = w;
    } else if (t < 288 + 18576 + 32) {
        int c = t - (288 + 18576);
        float inv = __fdiv_rn(g1[c], __fsqrt_rn(__fadd_rn(v1[c], 1e-5f)));
        g_inv1[c] = inv;
        g_sh1[c]  = __fsub_rn(be1[c], __fmul_rn(m1[c], inv));
    } else if (t < 288 + 18576 + 64) {
        int c = t - (288 + 18576 + 32);
        float inv = __fdiv_rn(g2[c], __fsqrt_rn(__fadd_rn(v2[c], 1e-5f)));
        g_inv2[c] = inv;
        g_sh2[c]  = __fsub_rn(be2[c], __fmul_rn(m2[c], inv));
    } else if (t < 288 + 18576 + 64 + 516) {
        int c = t - (288 + 18576 + 64);
        float inv = __fdiv_rn(g3[c], __fsqrt_rn(__fadd_rn(v3[c], 1e-5f)));
        g_sc3[c] = inv;
        g_sh3[c] = __fsub_rn(be3[c], __fmul_rn(m3[c], inv));
    } else if (t < 288 + 18576 + 64 + 516 + 2304) {
        // transpose w0 -> [k][oc] so per-CTA loads are linear/coalesced
        int j  = t - (288 + 18576 + 64 + 516);
        int oc = j & 31;
        int r  = j >> 5;
        int ic = r & 7;
        int kk = r >> 3;                  // ky*3+kx
        g_w0p[j] = w0[oc * 72 + ic * 9 + kk];
    }
}

// ---- f32x2 helpers (per-lane IEEE RN fma; bit-identical to scalar) ---------
__device__ __forceinline__ unsigned long long fma2(unsigned long long a,
                                                   unsigned long long b,
                                                   unsigned long long c) {
    unsigned long long d;
    asm("fma.rn.f32x2 %0, %1, %2, %3;" : "=l"(d) : "l"(a), "l"(b), "l"(c));
    return d;
}
__device__ __forceinline__ unsigned long long pack2(float lo, float hi) {
    unsigned long long r;
    asm("mov.b64 %0, {%1, %2};" : "=l"(r) : "f"(lo), "f"(hi));
    return r;
}
__device__ __forceinline__ float2 unpack2(unsigned long long v) {
    float lo, hi;
    asm("mov.b64 {%0, %1}, %2;" : "=f"(lo), "=f"(hi) : "l"(v));
    return make_float2(lo, hi);
}

#define XPITCH 17   // sx row pitch in floats

__global__ __launch_bounds__(256, 2) void fused_kernel(
        const float* __restrict__ x,
        const float* __restrict__ b0,
        const float* __restrict__ wlast,
        const float* __restrict__ blast,
        float* __restrict__ out) {
    __shared__ float    sx[8 * 16 * XPITCH];           // plain input image
    __shared__ __align__(16) float swp[2304];          // weights [k][oc]
    __shared__ uint32_t s1bits[196];                   // conv0 sign bits (bit=oc)
    __shared__ uint32_t sw2b[288];
    __shared__ __align__(16) uint32_t fcb[36];         // 1152 FC input bits
    __shared__ float    h3[516];
    __shared__ float    sb0[32], sinv1[32], ssh1[32];

    const int tid = threadIdx.x;
    const int img = blockIdx.x;

    // ---- Phase A: stage image, weights, constants; zero bit arrays ---------
    {
        const float4* xin = (const float4*)(x + (size_t)img * 2048);
        for (int i = tid; i < 512; i += 256) {
            float4 v = xin[i];
            int e  = i * 4;
            int ic = e >> 8;
            int rm = e & 255;
            int yy = rm >> 4;
            int xx = rm & 15;
            float* dst = &sx[(ic * 16 + yy) * XPITCH + xx];
            dst[0] = v.x; dst[1] = v.y; dst[2] = v.z; dst[3] = v.w;
        }
        for (int i = tid; i < 2304; i += 256) swp[i] = g_w0p[i];
        for (int i = tid; i < 288;  i += 256) sw2b[i] = g_w2bits[i];
        for (int i = tid; i < 196;  i += 256) s1bits[i] = 0u;
        if (tid < 36) fcb[tid] = 0u;
        if (tid < 32) {
            sb0[tid]   = b0[tid];
            sinv1[tid] = g_inv1[tid];
            ssh1[tid]  = g_sh1[tid];
        }
    }
    __syncthreads();

    // ---- Phase B: conv0, 16oc x 2x register tile, f32x2 over oc pairs ------
    // task = (h, xg, y): h = oc-half, xg = x pair, y = row. 196 tasks.
    // FMA chain per acc half: (ky,kx,ic) ascending, acc from 0 — as R6/R8.
    if (tid < 196) {
        int y  = tid % 14;
        int t2 = tid / 14;
        int xg = t2 % 7;
        int h  = t2 / 7;
        int x0 = 2 * xg;

        unsigned long long acc[16];          // [xi*8 + p], p = ocpair in half
        #pragma unroll
        for (int i = 0; i < 16; i++) acc[i] = 0ull;

        #pragma unroll
        for (int ky = 0; ky < 3; ky++) {
            #pragma unroll
            for (int kx = 0; kx < 3; kx++) {
                #pragma unroll
                for (int ic = 0; ic < 8; ic++) {
                    int k8 = (ky * 3 + kx) * 8 + ic;
                    const float* rr = &sx[(ic * 16 + y + ky) * XPITCH + x0 + kx];
                    float a = rr[0];
                    float b = rr[1];
                    unsigned long long s0 = pack2(a, a);   // splat via mov
                    unsigned long long s1 = pack2(b, b);
                    const ulonglong2* wq = (const ulonglong2*)&swp[k8 * 32 + h * 16];
                    ulonglong2 w01 = wq[0], w23 = wq[1], w45 = wq[2], w67 = wq[3];
                    acc[0]  = fma2(s0, w01.x, acc[0]);
                    acc[8]  = fma2(s1, w01.x, acc[8]);
                    acc[1]  = fma2(s0, w01.y, acc[1]);
                    acc[9]  = fma2(s1, w01.y, acc[9]);
                    acc[2]  = fma2(s0, w23.x, acc[2]);
                    acc[10] = fma2(s1, w23.x, acc[10]);
                    acc[3]  = fma2(s0, w23.y, acc[3]);
                    acc[11] = fma2(s1, w23.y, acc[11]);
                    acc[4]  = fma2(s0, w45.x, acc[4]);
                    acc[12] = fma2(s1, w45.x, acc[12]);
                    acc[5]  = fma2(s0, w45.y, acc[5]);
                    acc[13] = fma2(s1, w45.y, acc[13]);
                    acc[6]  = fma2(s0, w67.x, acc[6]);
                    acc[14] = fma2(s1, w67.x, acc[14]);
                    acc[7]  = fma2(s0, w67.y, acc[7]);
                    acc[15] = fma2(s1, w67.y, acc[15]);
                }
            }
        }
        // epilogue: bias + bn1 sign (unfused), 16-bit masks, one OR per x
        uint32_t m0 = 0u, m1 = 0u;
        #pragma unroll
        for (int p = 0; p < 8; p++) {
            float biasL = sb0[h * 16 + 2 * p],     biasH = sb0[h * 16 + 2 * p + 1];
            float invL  = sinv1[h * 16 + 2 * p],   invH  = sinv1[h * 16 + 2 * p + 1];
            float shL   = ssh1[h * 16 + 2 * p],    shH   = ssh1[h * 16 + 2 * p + 1];
            float2 a0 = unpack2(acc[p]);
            float2 a1 = unpack2(acc[8 + p]);
            if (__fadd_rn(__fmul_rn(__fadd_rn(a0.x, biasL), invL), shL) >= 0.f)
                m0 |= 1u << (2 * p);
            if (__fadd_rn(__fmul_rn(__fadd_rn(a0.y, biasH), invH), shH) >= 0.f)
                m0 |= 1u << (2 * p + 1);
            if (__fadd_rn(__fmul_rn(__fadd_rn(a1.x, biasL), invL), shL) >= 0.f)
                m1 |= 1u << (2 * p);
            if (__fadd_rn(__fmul_rn(__fadd_rn(a1.y, biasH), invH), shH) >= 0.f)
                m1 |= 1u << (2 * p + 1);
        }
        atomicOr(&s1bits[y * 14 + x0],     m0 << (16 * h));
        atomicOr(&s1bits[y * 14 + x0 + 1], m1 << (16 * h));
    }
    __syncthreads();

    // ---- Phase C: binary conv2 + maxpool + bn2 sign, sliding reg window ----
    // thread = (c, py): loads 4x14 strip of s1bits once, computes 6 pooled x.
    if (tid < 192) {
        int c  = tid / 6;
        int py = tid % 6;
        int y0 = 2 * py;

        uint32_t wk[9];
        #pragma unroll
        for (int k = 0; k < 9; k++) wk[k] = sw2b[c * 9 + k];

        uint32_t r[4][14];
        #pragma unroll
        for (int dy = 0; dy < 4; dy++)
            #pragma unroll
            for (int xx = 0; xx < 14; xx++)
                r[dy][xx] = s1bits[(y0 + dy) * 14 + xx];

        float inv = g_inv2[c], sh = g_sh2[c];
        uint32_t mask6 = 0u;
        #pragma unroll
        for (int px = 0; px < 6; px++) {
            int maxd = -10000;
            #pragma unroll
            for (int dy = 0; dy < 2; dy++) {
                #pragma unroll
                for (int dx = 0; dx < 2; dx++) {
                    int xx = 2 * px + dx;
                    int p = 0;
                    #pragma unroll
                    for (int ky = 0; ky < 3; ky++) {
                        #pragma unroll
                        for (int kx = 0; kx < 3; kx++)
                            p += __popc(r[dy + ky][xx + kx] ^ wk[ky * 3 + kx]);
                    }
                    int d = 288 - 2 * p;           // exact integer dot
                    maxd = max(maxd, d);
                }
            }
            float v = __fadd_rn(__fmul_rn((float)maxd, inv), sh);
            if (v >= 0.f) mask6 |= 1u << px;
        }
        int base = c * 36 + py * 6;
        int word = base >> 5;
        int off  = base & 31;
        atomicOr(&fcb[word], mask6 << off);
        if (off > 26)
            atomicOr(&fcb[word + 1], mask6 >> (32 - off));
    }
    __syncthreads();

    // ---- Phase D: binary FC (1152 -> 516, exact int) + bn3 + hardtanh ------
    for (int o = tid; o < 516; o += 256) {
        const uint4* wr  = (const uint4*)&g_wfcbits[o * 36];
        const uint4* fb4 = (const uint4*)fcb;
        int p = 0;
        #pragma unroll
        for (int q = 0; q < 9; q++) {
            uint4 wv = wr[q];
            uint4 fv = fb4[q];
            p += __popc(fv.x ^ wv.x) + __popc(fv.y ^ wv.y)
               + __popc(fv.z ^ wv.z) + __popc(fv.w ^ wv.w);
        }
        float d = (float)(1152 - 2 * p);
        float h = __fadd_rn(__fmul_rn(d, g_sc3[o]), g_sh3[o]);  // bn3 UNFUSED
        h3[o] = fminf(1.f, fmaxf(-1.f, h));
    }
    __syncthreads();

    // ---- Phase E: final 516x10 GEMV (fp32) + bias --------------------------
    if (tid < 160) {
        int i = tid >> 4;       // output index 0..9
        int s = tid & 15;       // 16-lane reduction slot
        const float* wr = wlast + i * 516;
        float acc = 0.f;
        for (int j = s; j < 516; j += 16)
            acc = __fmaf_rn(h3[j], wr[j], acc);
        #pragma unroll
        for (int off = 8; off; off >>= 1)
            acc = __fadd_rn(acc, __shfl_xor_sync(0xffffffffu, acc, off, 16));
        if (s == 0)
            out[(size_t)img * 10 + i] = __fadd_rn(acc, blast[i]);
    }
}

extern "C" void kernel_launch(void* const* d_in, const int* in_sizes, int n_in,
                              void* d_out, int out_size) {
    const float* x     = (const float*)d_in[0];
    const float* w0    = (const float*)d_in[1];
    const float* b0    = (const float*)d_in[2];
    const float* g1    = (const float*)d_in[3];
    const float* be1   = (const float*)d_in[4];
    const float* m1    = (const float*)d_in[5];
    const float* v1    = (const float*)d_in[6];
    const float* w2    = (const float*)d_in[7];
    const float* g2    = (const float*)d_in[8];
    const float* be2   = (const float*)d_in[9];
    const float* m2    = (const float*)d_in[10];
    const float* v2    = (const float*)d_in[11];
    const float* wfc   = (const float*)d_in[12];
    const float* g3    = (const float*)d_in[13];
    const float* be3   = (const float*)d_in[14];
    const float* m3    = (const float*)d_in[15];
    const float* v3    = (const float*)d_in[16];
    const float* wlast = (const float*)d_in[17];
    const float* blast = (const float*)d_in[18];
    float* out = (float*)d_out;

    // 288 + 18576 + 32 + 32 + 516 + 2304 = 21748 prep tasks
    prep_kernel<<<85, 256>>>(w0, w2, wfc, g1, be1, m1, v1,
                             g2, be2, m2, v2, g3, be3, m3, v3);
    fused_kernel<<<8192, 256>>>(x, b0, wlast, blast, out);
}

// round 11
// speedup vs baseline: 1.5514x; 1.1127x over previous
#include <cuda_runtime.h>
#include <cstdint>

// ---------------------------------------------------------------------------
// EMGNetQuantized fused BinaryNet inference, XLA-matched fp32 numerics.
// R11 = R10 with XPITCH 17 -> 20 so hoisted float4 window loads are 16B
// aligned (R10 trapped on misaligned LDS.128). conv0 tile = 8oc x 4x per
// thread, input window hoisted per (ky,ic) and reused across kx. FMA2 chains
// bit-identical to R6/R8/R9: (ky,kx,ic) ascending, acc from 0, bias after,
// unfused bn decisions. Phases A/C/D/E as R9.
// ---------------------------------------------------------------------------

__device__ __align__(16) uint32_t g_w2bits[32 * 9];       // [oc][ky*3+kx], bit=ic
__device__ __align__(16) uint32_t g_wfcbits[516 * 36];    // [o][word], bit=col%32
__device__ __align__(16) float    g_w0p[2304];            // [k=(ky3+kx)*8+ic][oc]
__device__ float g_inv1[32], g_sh1[32];                   // bn1 scale/shift
__device__ float g_inv2[32], g_sh2[32];                   // bn2 scale/shift
__device__ float g_sc3[516], g_sh3[516];                  // bn3 scale/shift

__global__ void prep_kernel(const float* __restrict__ w0,
                            const float* __restrict__ w2,
                            const float* __restrict__ wfc,
                            const float* __restrict__ g1, const float* __restrict__ be1,
                            const float* __restrict__ m1, const float* __restrict__ v1,
                            const float* __restrict__ g2, const float* __restrict__ be2,
                            const float* __restrict__ m2, const float* __restrict__ v2,
                            const float* __restrict__ g3, const float* __restrict__ be3,
                            const float* __restrict__ m3, const float* __restrict__ v3) {
    int t = blockIdx.x * blockDim.x + threadIdx.x;
    if (t < 288) {
        int oc = t / 9, k = t % 9;
        uint32_t w = 0u;
        #pragma unroll 4
        for (int ic = 0; ic < 32; ic++)
            if (w2[oc * 288 + ic * 9 + k] >= 0.f) w |= (1u << ic);
        g_w2bits[t] = w;
    } else if (t < 288 + 18576) {
        int j = t - 288;
        int o = j / 36, c = j % 36;
        const float* row = wfc + o * 1152 + c * 32;
        uint32_t w = 0u;
        #pragma unroll 4
        for (int b = 0; b < 32; b++)
            if (row[b] >= 0.f) w |= (1u << b);
        g_wfcbits[j] = w;
    } else if (t < 288 + 18576 + 32) {
        int c = t - (288 + 18576);
        float inv = __fdiv_rn(g1[c], __fsqrt_rn(__fadd_rn(v1[c], 1e-5f)));
        g_inv1[c] = inv;
        g_sh1[c]  = __fsub_rn(be1[c], __fmul_rn(m1[c], inv));
    } else if (t < 288 + 18576 + 64) {
        int c = t - (288 + 18576 + 32);
        float inv = __fdiv_rn(g2[c], __fsqrt_rn(__fadd_rn(v2[c], 1e-5f)));
        g_inv2[c] = inv;
        g_sh2[c]  = __fsub_rn(be2[c], __fmul_rn(m2[c], inv));
    } else if (t < 288 + 18576 + 64 + 516) {
        int c = t - (288 + 18576 + 64);
        float inv = __fdiv_rn(g3[c], __fsqrt_rn(__fadd_rn(v3[c], 1e-5f)));
        g_sc3[c] = inv;
        g_sh3[c] = __fsub_rn(be3[c], __fmul_rn(m3[c], inv));
    } else if (t < 288 + 18576 + 64 + 516 + 2304) {
        // transpose w0 -> [k][oc] so per-CTA loads are linear/coalesced
        int j  = t - (288 + 18576 + 64 + 516);
        int oc = j & 31;
        int r  = j >> 5;
        int ic = r & 7;
        int kk = r >> 3;                  // ky*3+kx
        g_w0p[j] = w0[oc * 72 + ic * 9 + kk];
    }
}

// ---- f32x2 helpers (per-lane IEEE RN fma; bit-identical to scalar) ---------
__device__ __forceinline__ unsigned long long fma2(unsigned long long a,
                                                   unsigned long long b,
                                                   unsigned long long c) {
    unsigned long long d;
    asm("fma.rn.f32x2 %0, %1, %2, %3;" : "=l"(d) : "l"(a), "l"(b), "l"(c));
    return d;
}
__device__ __forceinline__ unsigned long long pack2(float lo, float hi) {
    unsigned long long r;
    asm("mov.b64 %0, {%1, %2};" : "=l"(r) : "f"(lo), "f"(hi));
    return r;
}
__device__ __forceinline__ float2 unpack2(unsigned long long v) {
    float lo, hi;
    asm("mov.b64 {%0, %1}, %2;" : "=f"(lo), "=f"(hi) : "l"(v));
    return make_float2(lo, hi);
}

#define XPITCH 20   // sx row pitch in floats: multiple of 4 -> 16B-aligned rows

__global__ __launch_bounds__(256, 2) void fused_kernel(
        const float* __restrict__ x,
        const float* __restrict__ b0,
        const float* __restrict__ wlast,
        const float* __restrict__ blast,
        float* __restrict__ out) {
    __shared__ __align__(16) float sx[8 * 16 * XPITCH + 8];  // +pad for 6-wide window
    __shared__ __align__(16) float swp[2304];                // weights [k][oc]
    __shared__ uint32_t s1bits[196];                         // conv0 sign bits (bit=oc)
    __shared__ uint32_t sw2b[288];
    __shared__ __align__(16) uint32_t fcb[36];               // 1152 FC input bits
    __shared__ float    h3[516];
    __shared__ float    sb0[32], sinv1[32], ssh1[32];

    const int tid = threadIdx.x;
    const int img = blockIdx.x;

    // ---- Phase A: stage image, weights, constants; zero bit arrays ---------
    {
        const float4* xin = (const float4*)(x + (size_t)img * 2048);
        for (int i = tid; i < 512; i += 256) {
            float4 v = xin[i];
            int e  = i * 4;
            int ic = e >> 8;
            int rm = e & 255;
            int yy = rm >> 4;
            int xx = rm & 15;
            // xx multiple of 4, row base multiple of 20 floats (16B aligned)
            *(float4*)&sx[(ic * 16 + yy) * XPITCH + xx] = v;
        }
        for (int i = tid; i < 2304; i += 256) swp[i] = g_w0p[i];
        for (int i = tid; i < 288;  i += 256) sw2b[i] = g_w2bits[i];
        for (int i = tid; i < 196;  i += 256) s1bits[i] = 0u;
        if (tid < 36) fcb[tid] = 0u;
        if (tid < 32) {
            sb0[tid]   = b0[tid];
            sinv1[tid] = g_inv1[tid];
            ssh1[tid]  = g_sh1[tid];
        }
    }
    __syncthreads();

    // ---- Phase B: conv0, 8oc x 4x tile, per-ky hoisted input window --------
    // task = (q, xgg, y): q = oc quarter (8 ocs = 4 f32x2 pairs),
    // xgg = x group (x0 = 4*xgg; xgg==3 has only 2 live outputs), y = row.
    // FMA chain per acc: (ky,kx,ic) ascending, acc from 0 — bit-exact.
    if (tid < 224) {
        int y   = tid % 14;
        int t2  = tid / 14;          // 0..15
        int xgg = t2 & 3;
        int q   = t2 >> 2;           // 0..3
        int x0  = 4 * xgg;
        int nx  = (xgg == 3) ? 2 : 4;

        unsigned long long acc[16];  // acc[p*4+j], p=ocpair in quarter, j=x
        #pragma unroll
        for (int i = 0; i < 16; i++) acc[i] = 0ull;

        #pragma unroll
        for (int ky = 0; ky < 3; ky++) {
            // hoist the 6-wide input window for all 8 ic (reused across kx)
            float sv[8][6];
            #pragma unroll
            for (int ic = 0; ic < 8; ic++) {
                const float* rr = &sx[(ic * 16 + y + ky) * XPITCH + x0];
                float4 v4 = *(const float4*)rr;        // 16B aligned (XPITCH=20)
                float2 v2 = *(const float2*)(rr + 4);  // 8B aligned
                sv[ic][0] = v4.x; sv[ic][1] = v4.y; sv[ic][2] = v4.z;
                sv[ic][3] = v4.w; sv[ic][4] = v2.x; sv[ic][5] = v2.y;
            }
            #pragma unroll
            for (int kx = 0; kx < 3; kx++) {
                #pragma unroll
                for (int ic = 0; ic < 8; ic++) {
                    int k8 = (ky * 3 + kx) * 8 + ic;
                    const ulonglong2* wq =
                        (const ulonglong2*)&swp[k8 * 32 + q * 8];
                    ulonglong2 wA = wq[0];     // oc pairs 0,1 of quarter
                    ulonglong2 wB = wq[1];     // oc pairs 2,3
                    unsigned long long s0 = pack2(sv[ic][kx],     sv[ic][kx]);
                    unsigned long long s1 = pack2(sv[ic][kx + 1], sv[ic][kx + 1]);
                    unsigned long long s2 = pack2(sv[ic][kx + 2], sv[ic][kx + 2]);
                    unsigned long long s3 = pack2(sv[ic][kx + 3], sv[ic][kx + 3]);
                    acc[0]  = fma2(s0, wA.x, acc[0]);
                    acc[1]  = fma2(s1, wA.x, acc[1]);
                    acc[2]  = fma2(s2, wA.x, acc[2]);
                    acc[3]  = fma2(s3, wA.x, acc[3]);
                    acc[4]  = fma2(s0, wA.y, acc[4]);
                    acc[5]  = fma2(s1, wA.y, acc[5]);
                    acc[6]  = fma2(s2, wA.y, acc[6]);
                    acc[7]  = fma2(s3, wA.y, acc[7]);
                    acc[8]  = fma2(s0, wB.x, acc[8]);
                    acc[9]  = fma2(s1, wB.x, acc[9]);
                    acc[10] = fma2(s2, wB.x, acc[10]);
                    acc[11] = fma2(s3, wB.x, acc[11]);
                    acc[12] = fma2(s0, wB.y, acc[12]);
                    acc[13] = fma2(s1, wB.y, acc[13]);
                    acc[14] = fma2(s2, wB.y, acc[14]);
                    acc[15] = fma2(s3, wB.y, acc[15]);
                }
            }
        }
        // epilogue: bias + bn1 sign (unfused), 8-bit masks per x, one OR each
        uint32_t mj[4] = {0u, 0u, 0u, 0u};
        #pragma unroll
        for (int p = 0; p < 4; p++) {
            int ocL = q * 8 + 2 * p;
            float biasL = sb0[ocL],     biasH = sb0[ocL + 1];
            float invL  = sinv1[ocL],   invH  = sinv1[ocL + 1];
            float shL   = ssh1[ocL],    shH   = ssh1[ocL + 1];
            #pragma unroll
            for (int j = 0; j < 4; j++) {
                float2 a = unpack2(acc[p * 4 + j]);
                if (__fadd_rn(__fmul_rn(__fadd_rn(a.x, biasL), invL), shL) >= 0.f)
                    mj[j] |= 1u << (2 * p);
                if (__fadd_rn(__fmul_rn(__fadd_rn(a.y, biasH), invH), shH) >= 0.f)
                    mj[j] |= 1u << (2 * p + 1);
            }
        }
        #pragma unroll
        for (int j = 0; j < 4; j++)
            if (j < nx)
                atomicOr(&s1bits[y * 14 + x0 + j], mj[j] << (8 * q));
    }
    __syncthreads();

    // ---- Phase C: binary conv2 + maxpool + bn2 sign, sliding reg window ----
    // thread = (c, py): loads 4x14 strip of s1bits once, computes 6 pooled x.
    if (tid < 192) {
        int c  = tid / 6;
        int py = tid % 6;
        int y0 = 2 * py;

        uint32_t wk[9];
        #pragma unroll
        for (int k = 0; k < 9; k++) wk[k] = sw2b[c * 9 + k];

        uint32_t r[4][14];
        #pragma unroll
        for (int dy = 0; dy < 4; dy++)
            #pragma unroll
            for (int xx = 0; xx < 14; xx++)
                r[dy][xx] = s1bits[(y0 + dy) * 14 + xx];

        float inv = g_inv2[c], sh = g_sh2[c];
        uint32_t mask6 = 0u;
        #pragma unroll
        for (int px = 0; px < 6; px++) {
            int maxd = -10000;
            #pragma unroll
            for (int dy = 0; dy < 2; dy++) {
                #pragma unroll
                for (int dx = 0; dx < 2; dx++) {
                    int xx = 2 * px + dx;
                    int p = 0;
                    #pragma unroll
                    for (int ky = 0; ky < 3; ky++) {
                        #pragma unroll
                        for (int kx = 0; kx < 3; kx++)
                            p += __popc(r[dy + ky][xx + kx] ^ wk[ky * 3 + kx]);
                    }
                    int d = 288 - 2 * p;           // exact integer dot
                    maxd = max(maxd, d);
                }
            }
            float v = __fadd_rn(__fmul_rn((float)maxd, inv), sh);
            if (v >= 0.f) mask6 |= 1u << px;
        }
        int base = c * 36 + py * 6;
        int word = base >> 5;
        int off  = base & 31;
        atomicOr(&fcb[word], mask6 << off);
        if (off > 26)
            atomicOr(&fcb[word + 1], mask6 >> (32 - off));
    }
    __syncthreads();

    // ---- Phase D: binary FC (1152 -> 516, exact int) + bn3 + hardtanh ------
    for (int o = tid; o < 516; o += 256) {
        const uint4* wr  = (const uint4*)&g_wfcbits[o * 36];
        const uint4* fb4 = (const uint4*)fcb;
        int p = 0;
        #pragma unroll
        for (int q = 0; q < 9; q++) {
            uint4 wv = wr[q];
            uint4 fv = fb4[q];
            p += __popc(fv.x ^ wv.x) + __popc(fv.y ^ wv.y)
               + __popc(fv.z ^ wv.z) + __popc(fv.w ^ wv.w);
        }
        float d = (float)(1152 - 2 * p);
        float h = __fadd_rn(__fmul_rn(d, g_sc3[o]), g_sh3[o]);  // bn3 UNFUSED
        h3[o] = fminf(1.f, fmaxf(-1.f, h));
    }
    __syncthreads();

    // ---- Phase E: final 516x10 GEMV (fp32) + bias --------------------------
    if (tid < 160) {
        int i = tid >> 4;       // output index 0..9
        int s = tid & 15;       // 16-lane reduction slot
        const float* wr = wlast + i * 516;
        float acc = 0.f;
        for (int j = s; j < 516; j += 16)
            acc = __fmaf_rn(h3[j], wr[j], acc);
        #pragma unroll
        for (int off = 8; off; off >>= 1)
            acc = __fadd_rn(acc, __shfl_xor_sync(0xffffffffu, acc, off, 16));
        if (s == 0)
            out[(size_t)img * 10 + i] = __fadd_rn(acc, blast[i]);
    }
}

extern "C" void kernel_launch(void* const* d_in, const int* in_sizes, int n_in,
                              void* d_out, int out_size) {
    const float* x     = (const float*)d_in[0];
    const float* w0    = (const float*)d_in[1];
    const float* b0    = (const float*)d_in[2];
    const float* g1    = (const float*)d_in[3];
    const float* be1   = (const float*)d_in[4];
    const float* m1    = (const float*)d_in[5];
    const float* v1    = (const float*)d_in[6];
    const float* w2    = (const float*)d_in[7];
    const float* g2    = (const float*)d_in[8];
    const float* be2   = (const float*)d_in[9];
    const float* m2    = (const float*)d_in[10];
    const float* v2    = (const float*)d_in[11];
    const float* wfc   = (const float*)d_in[12];
    const float* g3    = (const float*)d_in[13];
    const float* be3   = (const float*)d_in[14];
    const float* m3    = (const float*)d_in[15];
    const float* v3    = (const float*)d_in[16];
    const float* wlast = (const float*)d_in[17];
    const float* blast = (const float*)d_in[18];
    float* out = (float*)d_out;

    // 288 + 18576 + 32 + 32 + 516 + 2304 = 21748 prep tasks
    prep_kernel<<<85, 256>>>(w0, w2, wfc, g1, be1, m1, v1,
                             g2, be2, m2, v2, g3, be3, m3, v3);
    fused_kernel<<<8192, 256>>>(x, b0, wlast, blast, out);
}